// round 1
// baseline (speedup 1.0000x reference)
#include <cuda_runtime.h>
#include <cuda_bf16.h>
#include <mma.h>

using namespace nvcuda;

#define BATCH  256
#define MSEL   128
#define DMODEL 2048
#define IFF    5504
#define MN     (MSEL*DMODEL)

// ---------------- scratch (device globals; no allocation) ----------------
__device__ float g_scores[BATCH];
__device__ int   g_sel[MSEL];
__device__ int   g_rank[BATCH];

__device__ float g_xsel[MSEL*DMODEL];
__device__ float g_x[MSEL*DMODEL];
__device__ float g_part[4*MSEL*DMODEL];
__device__ float g_gate[MSEL*IFF];
__device__ float g_up[MSEL*IFF];

__device__ __nv_bfloat16 g_h_hi[MSEL*DMODEL],  g_h_lo[MSEL*DMODEL];
__device__ __nv_bfloat16 g_v_hi[MSEL*DMODEL],  g_v_lo[MSEL*DMODEL];
__device__ __nv_bfloat16 g_h2_hi[MSEL*DMODEL], g_h2_lo[MSEL*DMODEL];
__device__ __nv_bfloat16 g_a_hi[MSEL*IFF],     g_a_lo[MSEL*IFF];

// ---------------- helpers ----------------
__device__ __forceinline__ void split_store(float v, __nv_bfloat16* hi_p, __nv_bfloat16* lo_p) {
    __nv_bfloat16 hi = __float2bfloat16(v);
    *hi_p = hi;
    *lo_p = __float2bfloat16(v - __bfloat162float(hi));
}

// ---------------- 1. router scores ----------------
__global__ __launch_bounds__(256) void k_router(const float* __restrict__ hid,
                                                const float* __restrict__ rw,
                                                const float* __restrict__ rb) {
    int b = blockIdx.x, t = threadIdx.x;
    const float4* hp = (const float4*)(hid + (size_t)b * DMODEL);
    const float4* wp = (const float4*)rw;
    float s = 0.f;
    #pragma unroll
    for (int i = 0; i < 2; i++) {
        float4 h = hp[t + i*256], w = wp[t + i*256];
        s += h.x*w.x + h.y*w.y + h.z*w.z + h.w*w.w;
    }
    __shared__ float red[256];
    red[t] = s; __syncthreads();
    for (int o = 128; o > 0; o >>= 1) { if (t < o) red[t] += red[t+o]; __syncthreads(); }
    if (t == 0) g_scores[b] = red[0] + rb[0];
}

// ---------------- 2. top-k selection (rank counting, deterministic) ----------------
__global__ __launch_bounds__(256) void k_select() {
    __shared__ float sc[BATCH];
    int t = threadIdx.x;
    sc[t] = g_scores[t];
    __syncthreads();
    float mine = sc[t];
    int r = 0;
    #pragma unroll 8
    for (int j = 0; j < BATCH; j++) {
        float v = sc[j];
        if (v > mine || (v == mine && j < t)) r++;
    }
    if (r < MSEL) { g_rank[t] = r; g_sel[r] = t; }
    else          { g_rank[t] = -1; }
}

// ---------------- 3. RMS norm (+optional gather) + bf16 split ----------------
// MODE 0: gather rows from hidden via g_sel, save x_sel, write g_h_hi/lo
// MODE 1: read g_x rows directly, write g_h2_hi/lo
template<int MODE>
__global__ __launch_bounds__(256) void k_rms(const float* __restrict__ src,
                                             const float* __restrict__ w) {
    int i = blockIdx.x, t = threadIdx.x;
    int row = (MODE == 0) ? g_sel[i] : i;
    const float* base = (MODE == 0) ? src : g_x;
    const float4* s4 = (const float4*)(base + (size_t)row * DMODEL);
    const float4* w4 = (const float4*)w;

    float4 v0 = s4[t], v1 = s4[t + 256];
    float ss = v0.x*v0.x + v0.y*v0.y + v0.z*v0.z + v0.w*v0.w
             + v1.x*v1.x + v1.y*v1.y + v1.z*v1.z + v1.w*v1.w;
    __shared__ float red[256];
    red[t] = ss; __syncthreads();
    for (int o = 128; o > 0; o >>= 1) { if (t < o) red[t] += red[t+o]; __syncthreads(); }
    __shared__ float rs_sh;
    if (t == 0) rs_sh = rsqrtf(red[0] * (1.0f/DMODEL) + 1e-6f);
    __syncthreads();
    float rs = rs_sh;

    if (MODE == 0) {
        float4* xo = (float4*)(g_xsel + (size_t)i * DMODEL);
        xo[t] = v0; xo[t + 256] = v1;
    }
    __nv_bfloat16* hh = (MODE == 0) ? g_h_hi : g_h2_hi;
    __nv_bfloat16* hl = (MODE == 0) ? g_h_lo : g_h2_lo;
    size_t o0 = (size_t)i * DMODEL + 4*t;
    size_t o1 = o0 + 1024;
    float4 w0 = w4[t], w1 = w4[t + 256];
    split_store(v0.x * rs * w0.x, hh+o0+0, hl+o0+0);
    split_store(v0.y * rs * w0.y, hh+o0+1, hl+o0+1);
    split_store(v0.z * rs * w0.z, hh+o0+2, hl+o0+2);
    split_store(v0.w * rs * w0.w, hh+o0+3, hl+o0+3);
    split_store(v1.x * rs * w1.x, hh+o1+0, hl+o1+0);
    split_store(v1.y * rs * w1.y, hh+o1+1, hl+o1+1);
    split_store(v1.z * rs * w1.z, hh+o1+2, hl+o1+2);
    split_store(v1.w * rs * w1.w, hh+o1+3, hl+o1+3);
}

// ---------------- 4. GEMM: C[128,N] = A[128,K] @ W[K,N], 3-term bf16 split -----
// BM=128, BN=64, BK=16, 256 threads (8 warps, 4(M) x 2(N), warp tile 32x32).
// which: 0 = h@wv -> g_part    1 = v@wo -> g_part
//        2 = h2@{w_gate,w_up} -> g_gate/g_up (dual weight, tiles split at ntiles0)
//        3 = act@w_down -> g_part
// split-K across gridDim.y into g_part[s] slabs (deterministic reduce later).
__global__ __launch_bounds__(256) void k_gemm(int which,
                                              const float* __restrict__ W0,
                                              const float* __restrict__ W1,
                                              int ntiles0, int Nld, int K) {
    int tile = blockIdx.x, s = blockIdx.y, S = gridDim.y;
    const __nv_bfloat16 *Ah, *Al;
    float* C;
    const float* W = W0;
    if (which == 0)      { Ah = g_h_hi;  Al = g_h_lo;  C = g_part; }
    else if (which == 1) { Ah = g_v_hi;  Al = g_v_lo;  C = g_part; }
    else if (which == 2) {
        Ah = g_h2_hi; Al = g_h2_lo;
        if (tile >= ntiles0) { W = W1; C = g_up; tile -= ntiles0; }
        else                 { C = g_gate; }
    }
    else                 { Ah = g_a_hi;  Al = g_a_lo;  C = g_part; }
    C += (size_t)s * MSEL * Nld;

    int n0 = tile * 64;
    int kchunk = K / S;
    int kbeg = s * kchunk, kend = kbeg + kchunk;

    int t = threadIdx.x;
    int arow = t >> 1, aseg = (t & 1) * 8;
    int wrow = t >> 4, wc = (t & 15) * 4;

    __shared__ __align__(16) __nv_bfloat16 sAh[128*16];
    __shared__ __align__(16) __nv_bfloat16 sAl[128*16];
    __shared__ __align__(16) __nv_bfloat16 sWh[16*64];
    __shared__ __align__(16) __nv_bfloat16 sWl[16*64];

    const __nv_bfloat16* Agh = Ah + (size_t)arow * K + aseg;
    const __nv_bfloat16* Agl = Al + (size_t)arow * K + aseg;
    const float*         Wg  = W  + (size_t)wrow * Nld + n0 + wc;

    uint4 rah, ral; float4 rw;

    wmma::fragment<wmma::accumulator,16,16,16,float> acc[2][2];
    #pragma unroll
    for (int i = 0; i < 2; i++)
        #pragma unroll
        for (int j = 0; j < 2; j++) wmma::fill_fragment(acc[i][j], 0.0f);

    int warp = t >> 5;
    int wm = warp & 3, wn = warp >> 2;

    // stage first tile
    rah = *(const uint4*)(Agh + kbeg);
    ral = *(const uint4*)(Agl + kbeg);
    rw  = *(const float4*)(Wg + (size_t)kbeg * Nld);

    for (int kk = kbeg; kk < kend; kk += 16) {
        // commit staged tile to smem
        *(uint4*)(sAh + arow*16 + aseg) = rah;
        *(uint4*)(sAl + arow*16 + aseg) = ral;
        float f[4] = {rw.x, rw.y, rw.z, rw.w};
        #pragma unroll
        for (int j = 0; j < 4; j++) {
            __nv_bfloat16 hi = __float2bfloat16(f[j]);
            sWh[wrow*64 + wc + j] = hi;
            sWl[wrow*64 + wc + j] = __float2bfloat16(f[j] - __bfloat162float(hi));
        }
        __syncthreads();

        // prefetch next tile into registers (overlaps with MMAs)
        if (kk + 16 < kend) {
            rah = *(const uint4*)(Agh + kk + 16);
            ral = *(const uint4*)(Agl + kk + 16);
            rw  = *(const float4*)(Wg + (size_t)(kk + 16) * Nld);
        }

        wmma::fragment<wmma::matrix_a,16,16,16,__nv_bfloat16,wmma::row_major> fah[2], fal[2];
        wmma::fragment<wmma::matrix_b,16,16,16,__nv_bfloat16,wmma::row_major> fbh[2], fbl[2];
        #pragma unroll
        for (int i = 0; i < 2; i++) {
            wmma::load_matrix_sync(fah[i], sAh + (wm*32 + i*16)*16, 16);
            wmma::load_matrix_sync(fal[i], sAl + (wm*32 + i*16)*16, 16);
        }
        #pragma unroll
        for (int j = 0; j < 2; j++) {
            wmma::load_matrix_sync(fbh[j], sWh + wn*32 + j*16, 64);
            wmma::load_matrix_sync(fbl[j], sWl + wn*32 + j*16, 64);
        }
        #pragma unroll
        for (int i = 0; i < 2; i++)
            #pragma unroll
            for (int j = 0; j < 2; j++) {
                wmma::mma_sync(acc[i][j], fah[i], fbh[j], acc[i][j]);
                wmma::mma_sync(acc[i][j], fah[i], fbl[j], acc[i][j]);
                wmma::mma_sync(acc[i][j], fal[i], fbh[j], acc[i][j]);
            }
        __syncthreads();
    }

    #pragma unroll
    for (int i = 0; i < 2; i++)
        #pragma unroll
        for (int j = 0; j < 2; j++)
            wmma::store_matrix_sync(C + (size_t)(wm*32 + i*16)*Nld + n0 + wn*32 + j*16,
                                    acc[i][j], Nld, wmma::mem_row_major);
}

// ---------------- epilogues ----------------
// v = sum(parts) + bv  -> split into g_v_hi/lo
__global__ __launch_bounds__(256) void k_epi_v(const float* __restrict__ bias) {
    int idx = blockIdx.x * 256 + threadIdx.x;
    float v = g_part[idx] + g_part[idx + MN] + g_part[idx + 2*MN] + g_part[idx + 3*MN]
            + bias[idx & (DMODEL - 1)];
    split_store(v, g_v_hi + idx, g_v_lo + idx);
}

// x = x_sel + sum(parts)  (o = v@wo)
__global__ __launch_bounds__(256) void k_epi_x() {
    int idx = blockIdx.x * 256 + threadIdx.x;
    g_x[idx] = g_xsel[idx] + g_part[idx] + g_part[idx + MN]
             + g_part[idx + 2*MN] + g_part[idx + 3*MN];
}

// act = silu(gate) * up -> split into g_a_hi/lo
__global__ __launch_bounds__(256) void k_epi_act() {
    int idx = blockIdx.x * 256 + threadIdx.x;
    float g = g_gate[idx], u = g_up[idx];
    float a = g * (1.0f / (1.0f + expf(-g))) * u;
    split_store(a, g_a_hi + idx, g_a_lo + idx);
}

// ---------------- final scatter: out = hidden, selected rows = x + mlp ----------------
__global__ __launch_bounds__(256) void k_final(const float* __restrict__ hid,
                                               float* __restrict__ out) {
    int b = blockIdx.x, t = threadIdx.x;
    int r = g_rank[b];
    if (r < 0) {
        const float4* s = (const float4*)(hid + (size_t)b * DMODEL);
        float4*       o = (float4*)(out + (size_t)b * DMODEL);
        o[t] = s[t];
        o[t + 256] = s[t + 256];
    } else {
        const float* xr = g_x + (size_t)r * DMODEL;
        const float* p  = g_part + (size_t)r * DMODEL;
        float* o = out + (size_t)b * DMODEL;
        #pragma unroll
        for (int c = 0; c < 8; c++) {
            int i = t + c * 256;
            o[i] = xr[i] + p[i] + p[i + MN] + p[i + 2*MN] + p[i + 3*MN];
        }
    }
}

// ---------------- launch ----------------
extern "C" void kernel_launch(void* const* d_in, const int* in_sizes, int n_in,
                              void* d_out, int out_size) {
    const float* hid = (const float*)d_in[0];
    // d_in[1]=cos, d_in[2]=sin : unused (T=1 => softmax over singleton => o = v@wo)
    const float* rw  = (const float*)d_in[3];
    const float* rb  = (const float*)d_in[4];
    const float* ln1 = (const float*)d_in[5];
    const float* ln2 = (const float*)d_in[6];
    // d_in[7..10] = wq,bq,wk,bk : unused
    const float* wv  = (const float*)d_in[11];
    const float* bv  = (const float*)d_in[12];
    const float* wo  = (const float*)d_in[13];
    const float* wg  = (const float*)d_in[14];
    const float* wu  = (const float*)d_in[15];
    const float* wd  = (const float*)d_in[16];
    float* out = (float*)d_out;

    k_router<<<BATCH, 256>>>(hid, rw, rb);
    k_select<<<1, 256>>>();
    k_rms<0><<<MSEL, 256>>>(hid, ln1);

    // v = h @ wv (+bv)            M=128 K=2048 N=2048, split-K=4
    k_gemm<<<dim3(32, 4), 256>>>(0, wv, nullptr, 32, DMODEL, DMODEL);
    k_epi_v<<<MN / 256, 256>>>(bv);

    // o = v @ wo ; x = x_sel + o
    k_gemm<<<dim3(32, 4), 256>>>(1, wo, nullptr, 32, DMODEL, DMODEL);
    k_epi_x<<<MN / 256, 256>>>();

    k_rms<1><<<MSEL, 256>>>(nullptr, ln2);

    // gate & up fused launch: N=5504 each, 86+86 tiles, no split-K
    k_gemm<<<dim3(172, 1), 256>>>(2, wg, wu, 86, IFF, DMODEL);
    k_epi_act<<<(MSEL * IFF) / 256, 256>>>();

    // down: K=5504, N=2048, split-K=4
    k_gemm<<<dim3(32, 4), 256>>>(3, wd, nullptr, 32, DMODEL, IFF);

    k_final<<<BATCH, 256>>>(hid, out);
}

// round 3
// speedup vs baseline: 1.9937x; 1.9937x over previous
#include <cuda_runtime.h>
#include <cuda_bf16.h>
#include <mma.h>

using namespace nvcuda;

#define BATCH  256
#define MSEL   128
#define DMODEL 2048
#define IFF    5504
#define MN     (MSEL*DMODEL)
#define NPART  8

// smem layout constants (GEMM)
#define A_LD   40      // 32 + 8 pad (bf16 elems)
#define W_LD   72      // 64 + 8 pad
#define A_STG  (128*A_LD)
#define W_STG  (32*W_LD)
#define SMEM_BYTES (2*A_STG*2*2 + 2*W_STG*2*2)   // (2 stages)*(hi+lo)*2B

// ---------------- scratch ----------------
__device__ float g_scores[BATCH];
__device__ int   g_sel[MSEL];
__device__ int   g_rank[BATCH];

__device__ float g_xsel[MSEL*DMODEL];
__device__ float g_x[MSEL*DMODEL];
__device__ float g_part[NPART*MSEL*DMODEL];
__device__ float g_gate[MSEL*IFF];
__device__ float g_up[MSEL*IFF];

__device__ __nv_bfloat16 g_h_hi[MSEL*DMODEL],  g_h_lo[MSEL*DMODEL];
__device__ __nv_bfloat16 g_v_hi[MSEL*DMODEL],  g_v_lo[MSEL*DMODEL];
__device__ __nv_bfloat16 g_h2_hi[MSEL*DMODEL], g_h2_lo[MSEL*DMODEL];
__device__ __nv_bfloat16 g_a_hi[MSEL*IFF],     g_a_lo[MSEL*IFF];

__device__ __forceinline__ void split_store(float v, __nv_bfloat16* hi_p, __nv_bfloat16* lo_p) {
    __nv_bfloat16 hi = __float2bfloat16(v);
    *hi_p = hi;
    *lo_p = __float2bfloat16(v - __bfloat162float(hi));
}

// ---------------- 1. router ----------------
__global__ __launch_bounds__(256) void k_router(const float* __restrict__ hid,
                                                const float* __restrict__ rw,
                                                const float* __restrict__ rb) {
    int b = blockIdx.x, t = threadIdx.x;
    const float4* hp = (const float4*)(hid + (size_t)b * DMODEL);
    const float4* wp = (const float4*)rw;
    float s = 0.f;
    #pragma unroll
    for (int i = 0; i < 2; i++) {
        float4 h = hp[t + i*256], w = wp[t + i*256];
        s += h.x*w.x + h.y*w.y + h.z*w.z + h.w*w.w;
    }
    __shared__ float red[256];
    red[t] = s; __syncthreads();
    for (int o = 128; o > 0; o >>= 1) { if (t < o) red[t] += red[t+o]; __syncthreads(); }
    if (t == 0) g_scores[b] = red[0] + rb[0];
}

// ---------------- 2. top-k (rank counting) ----------------
__global__ __launch_bounds__(256) void k_select() {
    __shared__ float sc[BATCH];
    int t = threadIdx.x;
    sc[t] = g_scores[t];
    __syncthreads();
    float mine = sc[t];
    int r = 0;
    #pragma unroll 8
    for (int j = 0; j < BATCH; j++) {
        float v = sc[j];
        if (v > mine || (v == mine && j < t)) r++;
    }
    if (r < MSEL) { g_rank[t] = r; g_sel[r] = t; }
    else          { g_rank[t] = -1; }
}

// ---------------- 3. RMS + bf16 split ----------------
template<int MODE>
__global__ __launch_bounds__(256) void k_rms(const float* __restrict__ src,
                                             const float* __restrict__ w) {
    int i = blockIdx.x, t = threadIdx.x;
    int row = (MODE == 0) ? g_sel[i] : i;
    const float* base = (MODE == 0) ? src : g_x;
    const float4* s4 = (const float4*)(base + (size_t)row * DMODEL);
    const float4* w4 = (const float4*)w;

    float4 v0 = s4[t], v1 = s4[t + 256];
    float ss = v0.x*v0.x + v0.y*v0.y + v0.z*v0.z + v0.w*v0.w
             + v1.x*v1.x + v1.y*v1.y + v1.z*v1.z + v1.w*v1.w;
    __shared__ float red[256];
    red[t] = ss; __syncthreads();
    for (int o = 128; o > 0; o >>= 1) { if (t < o) red[t] += red[t+o]; __syncthreads(); }
    __shared__ float rs_sh;
    if (t == 0) rs_sh = rsqrtf(red[0] * (1.0f/DMODEL) + 1e-6f);
    __syncthreads();
    float rs = rs_sh;

    if (MODE == 0) {
        float4* xo = (float4*)(g_xsel + (size_t)i * DMODEL);
        xo[t] = v0; xo[t + 256] = v1;
    }
    __nv_bfloat16* hh = (MODE == 0) ? g_h_hi : g_h2_hi;
    __nv_bfloat16* hl = (MODE == 0) ? g_h_lo : g_h2_lo;
    size_t o0 = (size_t)i * DMODEL + 4*t;
    size_t o1 = o0 + 1024;
    float4 w0 = w4[t], w1 = w4[t + 256];
    split_store(v0.x * rs * w0.x, hh+o0+0, hl+o0+0);
    split_store(v0.y * rs * w0.y, hh+o0+1, hl+o0+1);
    split_store(v0.z * rs * w0.z, hh+o0+2, hl+o0+2);
    split_store(v0.w * rs * w0.w, hh+o0+3, hl+o0+3);
    split_store(v1.x * rs * w1.x, hh+o1+0, hl+o1+0);
    split_store(v1.y * rs * w1.y, hh+o1+1, hl+o1+1);
    split_store(v1.z * rs * w1.z, hh+o1+2, hl+o1+2);
    split_store(v1.w * rs * w1.w, hh+o1+3, hl+o1+3);
}

// ---------------- 4. GEMM v2: BM=128 BN=64 BK=32, double-buffered, 1 sync/iter ----
// which: 0 = h@wv -> g_part   1 = v@wo -> g_part
//        2 = h2@{w_gate,w_up} -> g_gate/g_up
//        3 = act@w_down -> g_part
__global__ __launch_bounds__(256, 2) void k_gemm(int which,
                                                 const float* __restrict__ W0,
                                                 const float* __restrict__ W1,
                                                 int ntiles0, int Nld, int K,
                                                 int kchunk) {
    extern __shared__ __align__(16) char smem_raw[];
    __nv_bfloat16* sAh = (__nv_bfloat16*)smem_raw;       // 2 stages * A_STG
    __nv_bfloat16* sAl = sAh + 2*A_STG;
    __nv_bfloat16* sWh = sAl + 2*A_STG;                  // 2 stages * W_STG
    __nv_bfloat16* sWl = sWh + 2*W_STG;

    int tile = blockIdx.x, s = blockIdx.y;
    const __nv_bfloat16 *Ah, *Al;
    float* C;
    const float* W = W0;
    if (which == 0)      { Ah = g_h_hi;  Al = g_h_lo;  C = g_part; }
    else if (which == 1) { Ah = g_v_hi;  Al = g_v_lo;  C = g_part; }
    else if (which == 2) {
        Ah = g_h2_hi; Al = g_h2_lo;
        if (tile >= ntiles0) { W = W1; C = g_up; tile -= ntiles0; }
        else                 { C = g_gate; }
    }
    else                 { Ah = g_a_hi;  Al = g_a_lo;  C = g_part; }
    C += (size_t)s * MSEL * Nld;

    int n0 = tile * 64;
    int kbeg = s * kchunk;
    int kend = kbeg + kchunk; if (kend > K) kend = K;
    int niter = (kend - kbeg) >> 5;

    int t = threadIdx.x;
    int arow = t >> 1,  acol = (t & 1) * 16;
    int wrow = t >> 3,  wcol = (t & 7) * 8;
    int warp = t >> 5;
    int wm = warp & 3, wn = warp >> 2;

    const __nv_bfloat16* Agh = Ah + (size_t)arow * K + kbeg + acol;
    const __nv_bfloat16* Agl = Al + (size_t)arow * K + kbeg + acol;
    const float*         Wg  = W  + (size_t)(kbeg + wrow) * Nld + n0 + wcol;

    uint4 rah0, rah1, ral0, ral1;
    float4 rw0, rw1;

    wmma::fragment<wmma::accumulator,16,16,16,float> acc[2][2];
    #pragma unroll
    for (int i = 0; i < 2; i++)
        #pragma unroll
        for (int j = 0; j < 2; j++) wmma::fill_fragment(acc[i][j], 0.0f);

    auto LOADG = [&](int kl) {
        rah0 = *(const uint4*)(Agh + kl);
        rah1 = *(const uint4*)(Agh + kl + 8);
        ral0 = *(const uint4*)(Agl + kl);
        ral1 = *(const uint4*)(Agl + kl + 8);
        rw0  = *(const float4*)(Wg + (size_t)kl * Nld);
        rw1  = *(const float4*)(Wg + (size_t)kl * Nld + 4);
    };
    auto STORE = [&](int buf) {
        __nv_bfloat16* ah = sAh + buf*A_STG + arow*A_LD + acol;
        __nv_bfloat16* al = sAl + buf*A_STG + arow*A_LD + acol;
        *(uint4*)ah = rah0;  *(uint4*)(ah + 8) = rah1;
        *(uint4*)al = ral0;  *(uint4*)(al + 8) = ral1;
        float f[8] = {rw0.x, rw0.y, rw0.z, rw0.w, rw1.x, rw1.y, rw1.z, rw1.w};
        __nv_bfloat16* wh = sWh + buf*W_STG + wrow*W_LD + wcol;
        __nv_bfloat16* wl = sWl + buf*W_STG + wrow*W_LD + wcol;
        #pragma unroll
        for (int j = 0; j < 8; j++) {
            __nv_bfloat16 hi = __float2bfloat16(f[j]);
            wh[j] = hi;
            wl[j] = __float2bfloat16(f[j] - __bfloat162float(hi));
        }
    };
    auto DOMMA = [&](int buf) {
        const __nv_bfloat16* ahb = sAh + buf*A_STG + (wm*32)*A_LD;
        const __nv_bfloat16* alb = sAl + buf*A_STG + (wm*32)*A_LD;
        const __nv_bfloat16* whb = sWh + buf*W_STG + wn*32;
        const __nv_bfloat16* wlb = sWl + buf*W_STG + wn*32;
        #pragma unroll
        for (int ks = 0; ks < 2; ks++) {
            wmma::fragment<wmma::matrix_a,16,16,16,__nv_bfloat16,wmma::row_major> fah[2], fal[2];
            wmma::fragment<wmma::matrix_b,16,16,16,__nv_bfloat16,wmma::row_major> fbh[2], fbl[2];
            #pragma unroll
            for (int i = 0; i < 2; i++) {
                wmma::load_matrix_sync(fah[i], ahb + (i*16)*A_LD + ks*16, A_LD);
                wmma::load_matrix_sync(fal[i], alb + (i*16)*A_LD + ks*16, A_LD);
            }
            #pragma unroll
            for (int j = 0; j < 2; j++) {
                wmma::load_matrix_sync(fbh[j], whb + (ks*16)*W_LD + j*16, W_LD);
                wmma::load_matrix_sync(fbl[j], wlb + (ks*16)*W_LD + j*16, W_LD);
            }
            #pragma unroll
            for (int i = 0; i < 2; i++)
                #pragma unroll
                for (int j = 0; j < 2; j++) {
                    wmma::mma_sync(acc[i][j], fah[i], fbh[j], acc[i][j]);
                    wmma::mma_sync(acc[i][j], fah[i], fbl[j], acc[i][j]);
                    wmma::mma_sync(acc[i][j], fal[i], fbh[j], acc[i][j]);
                }
        }
    };

    LOADG(0);
    STORE(0);
    __syncthreads();

    for (int it = 0; it < niter; it++) {
        int cur = it & 1;
        if (it + 1 < niter) LOADG((it + 1) << 5);
        DOMMA(cur);
        if (it + 1 < niter) STORE(cur ^ 1);
        __syncthreads();
    }

    #pragma unroll
    for (int i = 0; i < 2; i++)
        #pragma unroll
        for (int j = 0; j < 2; j++)
            wmma::store_matrix_sync(C + (size_t)(wm*32 + i*16)*Nld + n0 + wn*32 + j*16,
                                    acc[i][j], Nld, wmma::mem_row_major);
}

// ---------------- epilogues ----------------
__global__ __launch_bounds__(256) void k_epi_v(const float* __restrict__ bias) {
    int idx = blockIdx.x * 256 + threadIdx.x;
    float v = bias[idx & (DMODEL - 1)];
    #pragma unroll
    for (int p = 0; p < NPART; p++) v += g_part[idx + p*MN];
    split_store(v, g_v_hi + idx, g_v_lo + idx);
}

__global__ __launch_bounds__(256) void k_epi_x() {
    int idx = blockIdx.x * 256 + threadIdx.x;
    float v = g_xsel[idx];
    #pragma unroll
    for (int p = 0; p < NPART; p++) v += g_part[idx + p*MN];
    g_x[idx] = v;
}

__global__ __launch_bounds__(256) void k_epi_act() {
    int idx = blockIdx.x * 256 + threadIdx.x;
    float g = g_gate[idx], u = g_up[idx];
    float a = g * (1.0f / (1.0f + expf(-g))) * u;
    split_store(a, g_a_hi + idx, g_a_lo + idx);
}

// ---------------- final scatter ----------------
__global__ __launch_bounds__(256) void k_final(const float* __restrict__ hid,
                                               float* __restrict__ out) {
    int b = blockIdx.x, t = threadIdx.x;
    int r = g_rank[b];
    if (r < 0) {
        const float4* s = (const float4*)(hid + (size_t)b * DMODEL);
        float4*       o = (float4*)(out + (size_t)b * DMODEL);
        o[t] = s[t];
        o[t + 256] = s[t + 256];
    } else {
        const float* xr = g_x + (size_t)r * DMODEL;
        const float* p  = g_part + (size_t)r * DMODEL;
        float* o = out + (size_t)b * DMODEL;
        #pragma unroll
        for (int c = 0; c < 8; c++) {
            int i = t + c * 256;
            float v = xr[i];
            #pragma unroll
            for (int q = 0; q < NPART; q++) v += p[i + q*MN];
            o[i] = v;
        }
    }
}

// ---------------- launch ----------------
extern "C" void kernel_launch(void* const* d_in, const int* in_sizes, int n_in,
                              void* d_out, int out_size) {
    const float* hid = (const float*)d_in[0];
    const float* rw  = (const float*)d_in[3];
    const float* rb  = (const float*)d_in[4];
    const float* ln1 = (const float*)d_in[5];
    const float* ln2 = (const float*)d_in[6];
    const float* wv  = (const float*)d_in[11];
    const float* bv  = (const float*)d_in[12];
    const float* wo  = (const float*)d_in[13];
    const float* wg  = (const float*)d_in[14];
    const float* wu  = (const float*)d_in[15];
    const float* wd  = (const float*)d_in[16];
    float* out = (float*)d_out;

    static bool attr_set = false;
    if (!attr_set) {
        cudaFuncSetAttribute(k_gemm, cudaFuncAttributeMaxDynamicSharedMemorySize, SMEM_BYTES);
        attr_set = true;
    }

    k_router<<<BATCH, 256>>>(hid, rw, rb);
    k_select<<<1, 256>>>();
    k_rms<0><<<MSEL, 256>>>(hid, ln1);

    // v = h @ wv (+bv): M=128 K=2048 N=2048, split-K=8 (kchunk=256)
    k_gemm<<<dim3(32, 8), 256, SMEM_BYTES>>>(0, wv, nullptr, 32, DMODEL, DMODEL, 256);
    k_epi_v<<<MN / 256, 256>>>(bv);

    // o = v @ wo ; x = x_sel + o
    k_gemm<<<dim3(32, 8), 256, SMEM_BYTES>>>(1, wo, nullptr, 32, DMODEL, DMODEL, 256);
    k_epi_x<<<MN / 256, 256>>>();

    k_rms<1><<<MSEL, 256>>>(nullptr, ln2);

    // gate & up fused: 86+86 column tiles, no split-K (kchunk=K)
    k_gemm<<<dim3(172, 1), 256, SMEM_BYTES>>>(2, wg, wu, 86, IFF, DMODEL, DMODEL);
    k_epi_act<<<(MSEL * IFF) / 256, 256>>>();

    // down: K=5504, N=2048, split-K=8 (kchunk=704, last slab 576)
    k_gemm<<<dim3(32, 8), 256, SMEM_BYTES>>>(3, wd, nullptr, 32, DMODEL, IFF, 704);

    k_final<<<BATCH, 256>>>(hid, out);
}

// round 5
// speedup vs baseline: 3.4716x; 1.7413x over previous
#include <cuda_runtime.h>
#include <cuda_bf16.h>
#include <cstdint>

#define BATCH  256
#define MSEL   128
#define DMODEL 2048
#define IFF    5504
#define MN     (MSEL*DMODEL)
#define MI     (MSEL*IFF)
#define NPART  8

// ---------------- GEMM geometry: BM=128 BN=64 BK=32, mma.sync m16n8k16 ----------------
#define ASTAGE 16384                 // 128 rows * 128B  ([hi 64B | lo 64B] per row)
#define WSTAGE 8192                  // hi 4KB + lo 4KB (32 rows * 128B each)
#define STAGEB (ASTAGE + WSTAGE)     // 24576
#define NSTG   3
#define GSMEM  (NSTG*STAGEB)         // 73728

#define SWZ(off) ((off) ^ (((off) >> 3) & 0x70))

// ---------------- scratch ----------------
__device__ float g_scores[BATCH];
__device__ int   g_sel[MSEL];
__device__ int   g_rank[BATCH];

__device__ float g_xsel[MSEL*DMODEL];
__device__ float g_x[MSEL*DMODEL];
__device__ float g_part[4*MI];       // 2.82M floats >= 8*MN; reused by all GEMMs

__device__ __nv_bfloat16 g_h_hi[MSEL*DMODEL],  g_h_lo[MSEL*DMODEL];
__device__ __nv_bfloat16 g_v_hi[MSEL*DMODEL],  g_v_lo[MSEL*DMODEL];
__device__ __nv_bfloat16 g_h2_hi[MSEL*DMODEL], g_h2_lo[MSEL*DMODEL];
__device__ __nv_bfloat16 g_a_hi[MSEL*IFF],     g_a_lo[MSEL*IFF];

// ---------------- helpers ----------------
__device__ __forceinline__ uint32_t s2u(const void* p) {
    uint32_t a;
    asm("{ .reg .u64 t; cvta.to.shared.u64 t, %1; cvt.u32.u64 %0, t; }" : "=r"(a) : "l"(p));
    return a;
}
__device__ __forceinline__ void cpa16(uint32_t dst, const void* src) {
    asm volatile("cp.async.cg.shared.global [%0], [%1], 16;" :: "r"(dst), "l"(src));
}
__device__ __forceinline__ void ldsm4(uint32_t* r, uint32_t a) {
    asm volatile("ldmatrix.sync.aligned.m8n8.x4.shared.b16 {%0,%1,%2,%3},[%4];"
        : "=r"(r[0]),"=r"(r[1]),"=r"(r[2]),"=r"(r[3]) : "r"(a));
}
__device__ __forceinline__ void ldsm4t(uint32_t* r, uint32_t a) {
    asm volatile("ldmatrix.sync.aligned.m8n8.x4.trans.shared.b16 {%0,%1,%2,%3},[%4];"
        : "=r"(r[0]),"=r"(r[1]),"=r"(r[2]),"=r"(r[3]) : "r"(a));
}
__device__ __forceinline__ void mma_bf16(float* c, const uint32_t* a, const uint32_t* b) {
    asm volatile("mma.sync.aligned.m16n8k16.row.col.f32.bf16.bf16.f32 "
        "{%0,%1,%2,%3},{%4,%5,%6,%7},{%8,%9},{%0,%1,%2,%3};"
        : "+f"(c[0]),"+f"(c[1]),"+f"(c[2]),"+f"(c[3])
        : "r"(a[0]),"r"(a[1]),"r"(a[2]),"r"(a[3]),"r"(b[0]),"r"(b[1]));
}
__device__ __forceinline__ void split_store(float v, __nv_bfloat16* hi_p, __nv_bfloat16* lo_p) {
    __nv_bfloat16 hi = __float2bfloat16(v);
    *hi_p = hi;
    *lo_p = __float2bfloat16(v - __bfloat162float(hi));
}

// ---------------- 1. router ----------------
__global__ __launch_bounds__(256) void k_router(const float* __restrict__ hid,
                                                const float* __restrict__ rw,
                                                const float* __restrict__ rb) {
    int b = blockIdx.x, t = threadIdx.x;
    const float4* hp = (const float4*)(hid + (size_t)b * DMODEL);
    const float4* wp = (const float4*)rw;
    float s = 0.f;
    #pragma unroll
    for (int i = 0; i < 2; i++) {
        float4 h = hp[t + i*256], w = wp[t + i*256];
        s += h.x*w.x + h.y*w.y + h.z*w.z + h.w*w.w;
    }
    __shared__ float red[256];
    red[t] = s; __syncthreads();
    for (int o = 128; o > 0; o >>= 1) { if (t < o) red[t] += red[t+o]; __syncthreads(); }
    if (t == 0) g_scores[b] = red[0] + rb[0];
}

// ---------------- 2. top-k (rank counting) ----------------
__global__ __launch_bounds__(256) void k_select() {
    __shared__ float sc[BATCH];
    int t = threadIdx.x;
    sc[t] = g_scores[t];
    __syncthreads();
    float mine = sc[t];
    int r = 0;
    #pragma unroll 8
    for (int j = 0; j < BATCH; j++) {
        float v = sc[j];
        if (v > mine || (v == mine && j < t)) r++;
    }
    if (r < MSEL) { g_rank[t] = r; g_sel[r] = t; }
    else          { g_rank[t] = -1; }
}

// ---------------- 3. RMS + bf16 split ----------------
template<int MODE>
__global__ __launch_bounds__(256) void k_rms(const float* __restrict__ src,
                                             const float* __restrict__ w) {
    int i = blockIdx.x, t = threadIdx.x;
    int row = (MODE == 0) ? g_sel[i] : i;
    const float* base = (MODE == 0) ? src : g_x;
    const float4* s4 = (const float4*)(base + (size_t)row * DMODEL);
    const float4* w4 = (const float4*)w;

    float4 v0 = s4[t], v1 = s4[t + 256];
    float ss = v0.x*v0.x + v0.y*v0.y + v0.z*v0.z + v0.w*v0.w
             + v1.x*v1.x + v1.y*v1.y + v1.z*v1.z + v1.w*v1.w;
    __shared__ float red[256];
    red[t] = ss; __syncthreads();
    for (int o = 128; o > 0; o >>= 1) { if (t < o) red[t] += red[t+o]; __syncthreads(); }
    __shared__ float rs_sh;
    if (t == 0) rs_sh = rsqrtf(red[0] * (1.0f/DMODEL) + 1e-6f);
    __syncthreads();
    float rs = rs_sh;

    if (MODE == 0) {
        float4* xo = (float4*)(g_xsel + (size_t)i * DMODEL);
        xo[t] = v0; xo[t + 256] = v1;
    }
    __nv_bfloat16* hh = (MODE == 0) ? g_h_hi : g_h2_hi;
    __nv_bfloat16* hl = (MODE == 0) ? g_h_lo : g_h2_lo;
    size_t o0 = (size_t)i * DMODEL + 4*t;
    size_t o1 = o0 + 1024;
    float4 w0 = w4[t], w1 = w4[t + 256];
    split_store(v0.x * rs * w0.x, hh+o0+0, hl+o0+0);
    split_store(v0.y * rs * w0.y, hh+o0+1, hl+o0+1);
    split_store(v0.z * rs * w0.z, hh+o0+2, hl+o0+2);
    split_store(v0.w * rs * w0.w, hh+o0+3, hl+o0+3);
    split_store(v1.x * rs * w1.x, hh+o1+0, hl+o1+0);
    split_store(v1.y * rs * w1.y, hh+o1+1, hl+o1+1);
    split_store(v1.z * rs * w1.z, hh+o1+2, hl+o1+2);
    split_store(v1.w * rs * w1.w, hh+o1+3, hl+o1+3);
}

// ---------------- 4. GEMM: mma.sync + swizzled smem + cp.async 3-stage ----------------
// C[128,N] = A[128,K] @ W[K,N], 3-term bf16 split (AhWh + AhWl + AlWh).
// which: 0 h@wv->part[s]  1 v@wo->part[s]  2 h2@{wg,wu}->part slabs {s, 2+s}  3 act@wd->part[s]
__global__ __launch_bounds__(256, 2) void k_gemm6(int which,
                                                  const float* __restrict__ W0,
                                                  const float* __restrict__ W1,
                                                  int ntiles0, int Nld, int K,
                                                  int kchunk) {
    extern __shared__ __align__(16) char smem[];
    uint32_t sb = s2u(smem);
    int t = threadIdx.x;
    int lane = t & 31, warp = t >> 5;
    int wm = warp & 3, wn = warp >> 2;

    int tile = blockIdx.x, s = blockIdx.y;
    const __nv_bfloat16 *Ah, *Al;
    float* C;
    const float* W = W0;
    if (which == 0)      { Ah = g_h_hi;  Al = g_h_lo;  C = g_part + (size_t)s * MSEL * Nld; }
    else if (which == 1) { Ah = g_v_hi;  Al = g_v_lo;  C = g_part + (size_t)s * MSEL * Nld; }
    else if (which == 2) {
        Ah = g_h2_hi; Al = g_h2_lo;
        if (tile >= ntiles0) { W = W1; tile -= ntiles0; C = g_part + (size_t)(2 + s) * MI; }
        else                 { C = g_part + (size_t)s * MI; }
    }
    else                 { Ah = g_a_hi;  Al = g_a_lo;  C = g_part + (size_t)s * MSEL * Nld; }

    int n0 = tile * 64;
    int kbeg = s * kchunk;
    int kend = kbeg + kchunk; if (kend > K) kend = K;
    int niter = (kend - kbeg) >> 5;

    // W fill mapping: 32 k-rows, 8 threads/row, 8 fp32 each
    int wk = t >> 3, wc = (t & 7) * 8;
    const float* Wg = W + (size_t)(kbeg + wk) * Nld + n0 + wc;

    float acc[2][4][4];
    #pragma unroll
    for (int i = 0; i < 2; i++)
        #pragma unroll
        for (int j = 0; j < 4; j++)
            #pragma unroll
            for (int q = 0; q < 4; q++) acc[i][j][q] = 0.f;

    float wreg[8];

    auto LOAD_A = [&](int it) {
        uint32_t stg = sb + (uint32_t)(it % NSTG) * STAGEB;
        int k0 = kbeg + (it << 5);
        #pragma unroll
        for (int c = 0; c < 4; c++) {
            int idx = c * 256 + t;
            int m = idx >> 3, j = idx & 7;
            const __nv_bfloat16* src = (j < 4 ? Ah : Al) + (size_t)m * K + k0 + (j & 3) * 8;
            cpa16(stg + SWZ((uint32_t)(m * 128 + j * 16)), src);
        }
        asm volatile("cp.async.commit_group;" ::: "memory");
    };
    auto LDG_W = [&](int it) {
        const float* p = Wg + (size_t)(it << 5) * Nld;
        float4 a = *(const float4*)p, b = *(const float4*)(p + 4);
        wreg[0]=a.x; wreg[1]=a.y; wreg[2]=a.z; wreg[3]=a.w;
        wreg[4]=b.x; wreg[5]=b.y; wreg[6]=b.z; wreg[7]=b.w;
    };
    auto STS_W = [&](int it) {
        uint32_t stg = sb + (uint32_t)(it % NSTG) * STAGEB + ASTAGE;
        uint32_t off = SWZ((uint32_t)(wk * 128 + wc * 2));
        uint32_t h[4], l[4];
        #pragma unroll
        for (int j = 0; j < 4; j++) {
            float f0 = wreg[2*j], f1 = wreg[2*j+1];
            h[j] = __byte_perm(__float_as_uint(f0), __float_as_uint(f1), 0x7632);
            float l0 = f0 - __uint_as_float(__float_as_uint(f0) & 0xFFFF0000u);
            float l1 = f1 - __uint_as_float(__float_as_uint(f1) & 0xFFFF0000u);
            asm("cvt.rn.bf16x2.f32 %0, %1, %2;" : "=r"(l[j]) : "f"(l1), "f"(l0));
        }
        asm volatile("st.shared.v4.b32 [%0], {%1,%2,%3,%4};"
            :: "r"(stg + off), "r"(h[0]), "r"(h[1]), "r"(h[2]), "r"(h[3]) : "memory");
        asm volatile("st.shared.v4.b32 [%0], {%1,%2,%3,%4};"
            :: "r"(stg + 4096 + off), "r"(l[0]), "r"(l[1]), "r"(l[2]), "r"(l[3]) : "memory");
    };

    int lrow = ((lane >> 3) & 1) * 8 + (lane & 7);
    int lseg = lane >> 4;

    auto DOMMA = [&](int it) {
        uint32_t stg = sb + (uint32_t)(it % NSTG) * STAGEB;
        uint32_t bh = stg + ASTAGE;
        uint32_t bl = bh + 4096;
        #pragma unroll
        for (int ks = 0; ks < 2; ks++) {
            uint32_t afh[2][4], afl[2][4];
            #pragma unroll
            for (int mt = 0; mt < 2; mt++) {
                int m = wm * 32 + mt * 16 + lrow;
                ldsm4(afh[mt], stg + SWZ((uint32_t)(m * 128 + ks * 32 + lseg * 16)));
                ldsm4(afl[mt], stg + SWZ((uint32_t)(m * 128 + 64 + ks * 32 + lseg * 16)));
            }
            uint32_t bfh[2][4], bfl[2][4];
            #pragma unroll
            for (int ntile = 0; ntile < 2; ntile++) {
                int kr = ks * 16 + lrow;
                uint32_t bd = SWZ((uint32_t)(kr * 128 + (wn * 32 + ntile * 16 + lseg * 8) * 2));
                ldsm4t(bfh[ntile], bh + bd);
                ldsm4t(bfl[ntile], bl + bd);
            }
            #pragma unroll
            for (int mt = 0; mt < 2; mt++)
                #pragma unroll
                for (int nt = 0; nt < 4; nt++) {
                    int n16 = nt >> 1, hh = nt & 1;
                    mma_bf16(acc[mt][nt], afh[mt], &bfh[n16][hh*2]);
                    mma_bf16(acc[mt][nt], afh[mt], &bfl[n16][hh*2]);
                    mma_bf16(acc[mt][nt], afl[mt], &bfh[n16][hh*2]);
                }
        }
    };

    // ---- preload stages 0,1 ----
    LOAD_A(0);
    LDG_W(0); STS_W(0);
    if (niter > 1) { LOAD_A(1); LDG_W(1); STS_W(1); }

    for (int it = 0; it < niter; it++) {
        if (it + 1 < niter) asm volatile("cp.async.wait_group 1;" ::: "memory");
        else                asm volatile("cp.async.wait_group 0;" ::: "memory");
        __syncthreads();
        if (it + 2 < niter) { LOAD_A(it + 2); LDG_W(it + 2); }
        DOMMA(it);
        if (it + 2 < niter) STS_W(it + 2);
    }

    // ---- epilogue: write fp32 partials ----
    int r0 = wm * 32 + (lane >> 2);
    int cb = n0 + wn * 32 + (lane & 3) * 2;
    #pragma unroll
    for (int mt = 0; mt < 2; mt++)
        #pragma unroll
        for (int nt = 0; nt < 4; nt++) {
            float* p = C + (size_t)(r0 + mt * 16) * Nld + cb + nt * 8;
            *(float2*)p = make_float2(acc[mt][nt][0], acc[mt][nt][1]);
            *(float2*)(p + 8 * (size_t)Nld) = make_float2(acc[mt][nt][2], acc[mt][nt][3]);
        }
}

// ---------------- epilogues ----------------
__global__ __launch_bounds__(256) void k_epi_v(const float* __restrict__ bias) {
    int idx = blockIdx.x * 256 + threadIdx.x;
    float v = bias[idx & (DMODEL - 1)];
    #pragma unroll
    for (int p = 0; p < NPART; p++) v += g_part[idx + p*MN];
    split_store(v, g_v_hi + idx, g_v_lo + idx);
}

__global__ __launch_bounds__(256) void k_epi_x() {
    int idx = blockIdx.x * 256 + threadIdx.x;
    float v = g_xsel[idx];
    #pragma unroll
    for (int p = 0; p < NPART; p++) v += g_part[idx + p*MN];
    g_x[idx] = v;
}

__global__ __launch_bounds__(256) void k_epi_act() {
    int idx = blockIdx.x * 256 + threadIdx.x;
    float g = g_part[idx] + g_part[idx + MI];
    float u = g_part[idx + 2*MI] + g_part[idx + 3*MI];
    float a = g * (1.0f / (1.0f + expf(-g))) * u;
    split_store(a, g_a_hi + idx, g_a_lo + idx);
}

// ---------------- final scatter ----------------
__global__ __launch_bounds__(256) void k_final(const float* __restrict__ hid,
                                               float* __restrict__ out) {
    int b = blockIdx.x, t = threadIdx.x;
    int r = g_rank[b];
    if (r < 0) {
        const float4* s = (const float4*)(hid + (size_t)b * DMODEL);
        float4*       o = (float4*)(out + (size_t)b * DMODEL);
        o[t] = s[t];
        o[t + 256] = s[t + 256];
    } else {
        const float* xr = g_x + (size_t)r * DMODEL;
        const float* p  = g_part + (size_t)r * DMODEL;
        float* o = out + (size_t)b * DMODEL;
        #pragma unroll
        for (int c = 0; c < 8; c++) {
            int i = t + c * 256;
            float v = xr[i];
            #pragma unroll
            for (int q = 0; q < NPART; q++) v += p[i + q*MN];
            o[i] = v;
        }
    }
}

// ---------------- launch ----------------
extern "C" void kernel_launch(void* const* d_in, const int* in_sizes, int n_in,
                              void* d_out, int out_size) {
    const float* hid = (const float*)d_in[0];
    const float* rw  = (const float*)d_in[3];
    const float* rb  = (const float*)d_in[4];
    const float* ln1 = (const float*)d_in[5];
    const float* ln2 = (const float*)d_in[6];
    const float* wv  = (const float*)d_in[11];
    const float* bv  = (const float*)d_in[12];
    const float* wo  = (const float*)d_in[13];
    const float* wg  = (const float*)d_in[14];
    const float* wu  = (const float*)d_in[15];
    const float* wd  = (const float*)d_in[16];
    float* out = (float*)d_out;

    static bool attr_set = false;
    if (!attr_set) {
        cudaFuncSetAttribute(k_gemm6, cudaFuncAttributeMaxDynamicSharedMemorySize, GSMEM);
        attr_set = true;
    }

    k_router<<<BATCH, 256>>>(hid, rw, rb);
    k_select<<<1, 256>>>();
    k_rms<0><<<MSEL, 256>>>(hid, ln1);

    // v = h @ wv (+bv): split-K=8 (kchunk=256, niter=8)
    k_gemm6<<<dim3(32, 8), 256, GSMEM>>>(0, wv, nullptr, 32, DMODEL, DMODEL, 256);
    k_epi_v<<<MN / 256, 256>>>(bv);

    // o = v @ wo ; x = x_sel + o
    k_gemm6<<<dim3(32, 8), 256, GSMEM>>>(1, wo, nullptr, 32, DMODEL, DMODEL, 256);
    k_epi_x<<<MN / 256, 256>>>();

    k_rms<1><<<MSEL, 256>>>(nullptr, ln2);

    // gate & up fused, split-K=2: grid (172,2), kchunk=1024 (niter=32)
    k_gemm6<<<dim3(172, 2), 256, GSMEM>>>(2, wg, wu, 86, IFF, DMODEL, 1024);
    k_epi_act<<<MI / 256, 256>>>();

    // down: K=5504, split-K=8 (kchunk=704; last slab 576)
    k_gemm6<<<dim3(32, 8), 256, GSMEM>>>(3, wd, nullptr, 32, DMODEL, IFF, 704);

    k_final<<<BATCH, 256>>>(hid, out);
}

// round 8
// speedup vs baseline: 4.6766x; 1.3471x over previous
#include <cuda_runtime.h>
#include <cuda_fp16.h>
#include <cstdint>

#define BATCH  256
#define MSEL   128
#define DMODEL 2048
#define IFF    5504
#define MN     (MSEL*DMODEL)
#define MI     (MSEL*IFF)
#define NPART  8

// ---------------- GEMM geometry: BM=128 BN=64 BK=32, mma.sync m16n8k16 fp16 ----------------
#define ASTAGE 16384                 // 128 rows * 128B  ([Ah 64B | Al 64B] per row)
#define WSTAGE 4096                  // 32 rows * 64 fp16 (128B/row)
#define STAGEB (ASTAGE + WSTAGE)     // 20480
#define NSTG   3
#define GSMEM  (NSTG*STAGEB)         // 61440

#define SWZ(off) ((off) ^ (((off) >> 3) & 0x70))

// ---------------- scratch ----------------
__device__ float g_scores[BATCH];
__device__ int   g_sel[MSEL];
__device__ int   g_rank[BATCH];

__device__ float g_xsel[MSEL*DMODEL];
__device__ float g_x[MSEL*DMODEL];
__device__ float g_part[6*MI];       // 6 slabs of MI >= 8 slabs of MN

__device__ __half g_h_hi[MSEL*DMODEL],  g_h_lo[MSEL*DMODEL];
__device__ __half g_v_hi[MSEL*DMODEL],  g_v_lo[MSEL*DMODEL];
__device__ __half g_h2_hi[MSEL*DMODEL], g_h2_lo[MSEL*DMODEL];
__device__ __half g_a_hi[MSEL*IFF],     g_a_lo[MSEL*IFF];

// ---------------- helpers ----------------
__device__ __forceinline__ uint32_t s2u(const void* p) {
    uint32_t a;
    asm("{ .reg .u64 t; cvta.to.shared.u64 t, %1; cvt.u32.u64 %0, t; }" : "=r"(a) : "l"(p));
    return a;
}
__device__ __forceinline__ void cpa16(uint32_t dst, const void* src) {
    asm volatile("cp.async.cg.shared.global [%0], [%1], 16;" :: "r"(dst), "l"(src));
}
__device__ __forceinline__ void ldsm4(uint32_t* r, uint32_t a) {
    asm volatile("ldmatrix.sync.aligned.m8n8.x4.shared.b16 {%0,%1,%2,%3},[%4];"
        : "=r"(r[0]),"=r"(r[1]),"=r"(r[2]),"=r"(r[3]) : "r"(a));
}
__device__ __forceinline__ void ldsm4t(uint32_t* r, uint32_t a) {
    asm volatile("ldmatrix.sync.aligned.m8n8.x4.trans.shared.b16 {%0,%1,%2,%3},[%4];"
        : "=r"(r[0]),"=r"(r[1]),"=r"(r[2]),"=r"(r[3]) : "r"(a));
}
__device__ __forceinline__ void mma_f16(float* c, const uint32_t* a, const uint32_t* b) {
    asm volatile("mma.sync.aligned.m16n8k16.row.col.f32.f16.f16.f32 "
        "{%0,%1,%2,%3},{%4,%5,%6,%7},{%8,%9},{%0,%1,%2,%3};"
        : "+f"(c[0]),"+f"(c[1]),"+f"(c[2]),"+f"(c[3])
        : "r"(a[0]),"r"(a[1]),"r"(a[2]),"r"(a[3]),"r"(b[0]),"r"(b[1]));
}
__device__ __forceinline__ void split_store(float v, __half* hi_p, __half* lo_p) {
    __half hi = __float2half_rn(v);
    *hi_p = hi;
    *lo_p = __float2half_rn(v - __half2float(hi));
}

// ---------------- 1. router ----------------
__global__ __launch_bounds__(256) void k_router(const float* __restrict__ hid,
                                                const float* __restrict__ rw,
                                                const float* __restrict__ rb) {
    int b = blockIdx.x, t = threadIdx.x;
    const float4* hp = (const float4*)(hid + (size_t)b * DMODEL);
    const float4* wp = (const float4*)rw;
    float s = 0.f;
    #pragma unroll
    for (int i = 0; i < 2; i++) {
        float4 h = hp[t + i*256], w = wp[t + i*256];
        s += h.x*w.x + h.y*w.y + h.z*w.z + h.w*w.w;
    }
    __shared__ float red[256];
    red[t] = s; __syncthreads();
    for (int o = 128; o > 0; o >>= 1) { if (t < o) red[t] += red[t+o]; __syncthreads(); }
    if (t == 0) g_scores[b] = red[0] + rb[0];
}

// ---------------- 2. top-k (rank counting) ----------------
__global__ __launch_bounds__(256) void k_select() {
    __shared__ float sc[BATCH];
    int t = threadIdx.x;
    sc[t] = g_scores[t];
    __syncthreads();
    float mine = sc[t];
    int r = 0;
    #pragma unroll 8
    for (int j = 0; j < BATCH; j++) {
        float v = sc[j];
        if (v > mine || (v == mine && j < t)) r++;
    }
    if (r < MSEL) { g_rank[t] = r; g_sel[r] = t; }
    else          { g_rank[t] = -1; }
}

// ---------------- 3. RMS + fp16 split ----------------
template<int MODE>
__global__ __launch_bounds__(256) void k_rms(const float* __restrict__ src,
                                             const float* __restrict__ w) {
    int i = blockIdx.x, t = threadIdx.x;
    int row = (MODE == 0) ? g_sel[i] : i;
    const float* base = (MODE == 0) ? src : g_x;
    const float4* s4 = (const float4*)(base + (size_t)row * DMODEL);
    const float4* w4 = (const float4*)w;

    float4 v0 = s4[t], v1 = s4[t + 256];
    float ss = v0.x*v0.x + v0.y*v0.y + v0.z*v0.z + v0.w*v0.w
             + v1.x*v1.x + v1.y*v1.y + v1.z*v1.z + v1.w*v1.w;
    __shared__ float red[256];
    red[t] = ss; __syncthreads();
    for (int o = 128; o > 0; o >>= 1) { if (t < o) red[t] += red[t+o]; __syncthreads(); }
    __shared__ float rs_sh;
    if (t == 0) rs_sh = rsqrtf(red[0] * (1.0f/DMODEL) + 1e-6f);
    __syncthreads();
    float rs = rs_sh;

    if (MODE == 0) {
        float4* xo = (float4*)(g_xsel + (size_t)i * DMODEL);
        xo[t] = v0; xo[t + 256] = v1;
    }
    __half* hh = (MODE == 0) ? g_h_hi : g_h2_hi;
    __half* hl = (MODE == 0) ? g_h_lo : g_h2_lo;
    size_t o0 = (size_t)i * DMODEL + 4*t;
    size_t o1 = o0 + 1024;
    float4 w0 = w4[t], w1 = w4[t + 256];
    split_store(v0.x * rs * w0.x, hh+o0+0, hl+o0+0);
    split_store(v0.y * rs * w0.y, hh+o0+1, hl+o0+1);
    split_store(v0.z * rs * w0.z, hh+o0+2, hl+o0+2);
    split_store(v0.w * rs * w0.w, hh+o0+3, hl+o0+3);
    split_store(v1.x * rs * w1.x, hh+o1+0, hl+o1+0);
    split_store(v1.y * rs * w1.y, hh+o1+1, hl+o1+1);
    split_store(v1.z * rs * w1.z, hh+o1+2, hl+o1+2);
    split_store(v1.w * rs * w1.w, hh+o1+3, hl+o1+3);
}

// ---------------- 4. GEMM: fp16 2-term, mma.sync, swizzled smem, cp.async ----------------
// C[128,N] = A[128,K] @ W[K,N], terms AhW + AlW (A split fp16, W single fp16).
// which: 0 h@wv->part[s]  1 v@wo->part[s]  2 h2@{wg,wu}->part slabs {s, 3+s}  3 act@wd->part[s]
__global__ __launch_bounds__(256, 2) void k_gemm7(int which,
                                                  const float* __restrict__ W0,
                                                  const float* __restrict__ W1,
                                                  int ntiles0, int Nld, int K,
                                                  int kchunk) {
    extern __shared__ __align__(16) char smem[];
    uint32_t sb = s2u(smem);
    int t = threadIdx.x;
    int lane = t & 31, warp = t >> 5;
    int wm = warp & 3, wn = warp >> 2;

    int tile = blockIdx.x, s = blockIdx.y;
    const __half *Ah, *Al;
    float* C;
    const float* W = W0;
    if (which == 0)      { Ah = g_h_hi;  Al = g_h_lo;  C = g_part + (size_t)s * MSEL * Nld; }
    else if (which == 1) { Ah = g_v_hi;  Al = g_v_lo;  C = g_part + (size_t)s * MSEL * Nld; }
    else if (which == 2) {
        Ah = g_h2_hi; Al = g_h2_lo;
        if (tile >= ntiles0) { W = W1; tile -= ntiles0; C = g_part + (size_t)(3 + s) * MI; }
        else                 { C = g_part + (size_t)s * MI; }
    }
    else                 { Ah = g_a_hi;  Al = g_a_lo;  C = g_part + (size_t)s * MSEL * Nld; }

    int n0 = tile * 64;
    int kbeg = s * kchunk;
    int kend = kbeg + kchunk; if (kend > K) kend = K;
    int niter = (kend - kbeg) >> 5;

    // W fill mapping: 32 k-rows, 8 threads/row, 8 fp32 each
    int wk = t >> 3, wc = (t & 7) * 8;
    const float* Wg = W + (size_t)(kbeg + wk) * Nld + n0 + wc;

    float acc[2][4][4];
    #pragma unroll
    for (int i = 0; i < 2; i++)
        #pragma unroll
        for (int j = 0; j < 4; j++)
            #pragma unroll
            for (int q = 0; q < 4; q++) acc[i][j][q] = 0.f;

    float wreg[8];

    auto LOAD_A = [&](int it) {
        uint32_t stg = sb + (uint32_t)(it % NSTG) * STAGEB;
        int k0 = kbeg + (it << 5);
        #pragma unroll
        for (int c = 0; c < 4; c++) {
            int idx = c * 256 + t;
            int m = idx >> 3, j = idx & 7;
            const __half* src = (j < 4 ? Ah : Al) + (size_t)m * K + k0 + (j & 3) * 8;
            cpa16(stg + SWZ((uint32_t)(m * 128 + j * 16)), src);
        }
        asm volatile("cp.async.commit_group;" ::: "memory");
    };
    auto LDG_W = [&](int it) {
        const float* p = Wg + (size_t)(it << 5) * Nld;
        float4 a = *(const float4*)p, b = *(const float4*)(p + 4);
        wreg[0]=a.x; wreg[1]=a.y; wreg[2]=a.z; wreg[3]=a.w;
        wreg[4]=b.x; wreg[5]=b.y; wreg[6]=b.z; wreg[7]=b.w;
    };
    auto STS_W = [&](int it) {
        uint32_t stg = sb + (uint32_t)(it % NSTG) * STAGEB + ASTAGE;
        uint32_t off = SWZ((uint32_t)(wk * 128 + wc * 2));
        uint32_t h[4];
        #pragma unroll
        for (int j = 0; j < 4; j++)
            asm("cvt.rn.f16x2.f32 %0, %1, %2;" : "=r"(h[j]) : "f"(wreg[2*j+1]), "f"(wreg[2*j]));
        asm volatile("st.shared.v4.b32 [%0], {%1,%2,%3,%4};"
            :: "r"(stg + off), "r"(h[0]), "r"(h[1]), "r"(h[2]), "r"(h[3]) : "memory");
    };

    int lrow = ((lane >> 3) & 1) * 8 + (lane & 7);
    int lseg = lane >> 4;

    auto DOMMA = [&](int it) {
        uint32_t stg = sb + (uint32_t)(it % NSTG) * STAGEB;
        uint32_t bw = stg + ASTAGE;
        #pragma unroll
        for (int ks = 0; ks < 2; ks++) {
            uint32_t afh[2][4], afl[2][4];
            #pragma unroll
            for (int mt = 0; mt < 2; mt++) {
                int m = wm * 32 + mt * 16 + lrow;
                ldsm4(afh[mt], stg + SWZ((uint32_t)(m * 128 + ks * 32 + lseg * 16)));
                ldsm4(afl[mt], stg + SWZ((uint32_t)(m * 128 + 64 + ks * 32 + lseg * 16)));
            }
            uint32_t bf[2][4];
            #pragma unroll
            for (int ntile = 0; ntile < 2; ntile++) {
                int kr = ks * 16 + lrow;
                uint32_t bd = SWZ((uint32_t)(kr * 128 + (wn * 32 + ntile * 16 + lseg * 8) * 2));
                ldsm4t(bf[ntile], bw + bd);
            }
            #pragma unroll
            for (int mt = 0; mt < 2; mt++)
                #pragma unroll
                for (int nt = 0; nt < 4; nt++) {
                    int n16 = nt >> 1, hh = nt & 1;
                    mma_f16(acc[mt][nt], afh[mt], &bf[n16][hh*2]);
                    mma_f16(acc[mt][nt], afl[mt], &bf[n16][hh*2]);
                }
        }
    };

    // ---- prologue: stage 0 fully, stage 1 A in flight + W in regs ----
    LDG_W(0); STS_W(0);
    LOAD_A(0);
    if (niter > 1) { LDG_W(1); LOAD_A(1); }

    for (int it = 0; it < niter; it++) {
        if (it + 1 < niter) asm volatile("cp.async.wait_group 1;" ::: "memory");
        else                asm volatile("cp.async.wait_group 0;" ::: "memory");
        __syncthreads();
        if (it + 1 < niter) STS_W(it + 1);                  // regs loaded last iter
        if (it + 2 < niter) { LOAD_A(it + 2); LDG_W(it + 2); }
        DOMMA(it);
    }

    // ---- epilogue: write fp32 partials ----
    int r0 = wm * 32 + (lane >> 2);
    int cb = n0 + wn * 32 + (lane & 3) * 2;
    #pragma unroll
    for (int mt = 0; mt < 2; mt++)
        #pragma unroll
        for (int nt = 0; nt < 4; nt++) {
            float* p = C + (size_t)(r0 + mt * 16) * Nld + cb + nt * 8;
            *(float2*)p = make_float2(acc[mt][nt][0], acc[mt][nt][1]);
            *(float2*)(p + 8 * (size_t)Nld) = make_float2(acc[mt][nt][2], acc[mt][nt][3]);
        }
}

// ---------------- epilogues ----------------
__global__ __launch_bounds__(256) void k_epi_v(const float* __restrict__ bias) {
    int idx = blockIdx.x * 256 + threadIdx.x;
    float v = bias[idx & (DMODEL - 1)];
    #pragma unroll
    for (int p = 0; p < NPART; p++) v += g_part[idx + p*MN];
    split_store(v, g_v_hi + idx, g_v_lo + idx);
}

__global__ __launch_bounds__(256) void k_epi_x() {
    int idx = blockIdx.x * 256 + threadIdx.x;
    float v = g_xsel[idx];
    #pragma unroll
    for (int p = 0; p < NPART; p++) v += g_part[idx + p*MN];
    g_x[idx] = v;
}

__global__ __launch_bounds__(256) void k_epi_act() {
    int idx = blockIdx.x * 256 + threadIdx.x;
    float g = g_part[idx] + g_part[idx + MI] + g_part[idx + 2*MI];
    float u = g_part[idx + 3*MI] + g_part[idx + 4*MI] + g_part[idx + 5*MI];
    float a = g * (1.0f / (1.0f + expf(-g))) * u;
    split_store(a, g_a_hi + idx, g_a_lo + idx);
}

// ---------------- final scatter ----------------
__global__ __launch_bounds__(256) void k_final(const float* __restrict__ hid,
                                               float* __restrict__ out) {
    int b = blockIdx.x, t = threadIdx.x;
    int r = g_rank[b];
    if (r < 0) {
        const float4* s = (const float4*)(hid + (size_t)b * DMODEL);
        float4*       o = (float4*)(out + (size_t)b * DMODEL);
        o[t] = s[t];
        o[t + 256] = s[t + 256];
    } else {
        const float* xr = g_x + (size_t)r * DMODEL;
        const float* p  = g_part + (size_t)r * DMODEL;
        float* o = out + (size_t)b * DMODEL;
        #pragma unroll
        for (int c = 0; c < 8; c++) {
            int i = t + c * 256;
            float v = xr[i];
            #pragma unroll
            for (int q = 0; q < NPART; q++) v += p[i + q*MN];
            o[i] = v;
        }
    }
}

// ---------------- launch ----------------
extern "C" void kernel_launch(void* const* d_in, const int* in_sizes, int n_in,
                              void* d_out, int out_size) {
    const float* hid = (const float*)d_in[0];
    const float* rw  = (const float*)d_in[3];
    const float* rb  = (const float*)d_in[4];
    const float* ln1 = (const float*)d_in[5];
    const float* ln2 = (const float*)d_in[6];
    const float* wv  = (const float*)d_in[11];
    const float* bv  = (const float*)d_in[12];
    const float* wo  = (const float*)d_in[13];
    const float* wg  = (const float*)d_in[14];
    const float* wu  = (const float*)d_in[15];
    const float* wd  = (const float*)d_in[16];
    float* out = (float*)d_out;

    static bool attr_set = false;
    if (!attr_set) {
        cudaFuncSetAttribute(k_gemm7, cudaFuncAttributeMaxDynamicSharedMemorySize, GSMEM);
        attr_set = true;
    }

    k_router<<<BATCH, 256>>>(hid, rw, rb);
    k_select<<<1, 256>>>();
    k_rms<0><<<MSEL, 256>>>(hid, ln1);

    // v = h @ wv (+bv): split-K=8 (kchunk=256, niter=8)
    k_gemm7<<<dim3(32, 8), 256, GSMEM>>>(0, wv, nullptr, 32, DMODEL, DMODEL, 256);
    k_epi_v<<<MN / 256, 256>>>(bv);

    // o = v @ wo ; x = x_sel + o
    k_gemm7<<<dim3(32, 8), 256, GSMEM>>>(1, wo, nullptr, 32, DMODEL, DMODEL, 256);
    k_epi_x<<<MN / 256, 256>>>();

    k_rms<1><<<MSEL, 256>>>(nullptr, ln2);

    // gate & up fused, split-K=3: grid (172,3), kchunk=704 (niter 22/22/20)
    k_gemm7<<<dim3(172, 3), 256, GSMEM>>>(2, wg, wu, 86, IFF, DMODEL, 704);
    k_epi_act<<<MI / 256, 256>>>();

    // down: K=5504, split-K=8 (kchunk=704; last slab 576)
    k_gemm7<<<dim3(32, 8), 256, GSMEM>>>(3, wd, nullptr, 32, DMODEL, IFF, 704);

    k_final<<<BATCH, 256>>>(hid, out);
}